// round 2
// baseline (speedup 1.0000x reference)
#include <cuda_runtime.h>
#include <cuda_bf16.h>

// Problem constants
#define BB 2
#define LL 2048
#define DD 2048
#define HH 16
#define HD 128
#define TT (BB*LL)            // 4096 tokens
#define QKVN (3*DD)           // 6144
#define OUT_ELEMS ((long)TT*DD)          // 8388608
#define SCORE_ELEMS ((long)BB*HH*LL*LL)  // 134217728

// Scratch (device globals; no allocation allowed)
__device__ float g_xn[TT*DD];
__device__ float g_qkv[TT*QKVN];
__device__ float g_attn[TT*DD];
__device__ float g_after[TT*DD];
__device__ float g_yn[TT*DD];
__device__ float g_hidden[TT*DD];
__device__ float g_hg[TT*DD];

// ---------------------------------------------------------------------------
// Block reductions (256 threads = 8 warps)
// ---------------------------------------------------------------------------
__device__ __forceinline__ float block_reduce_max(float v, float* red) {
    int lane = threadIdx.x & 31, wid = threadIdx.x >> 5;
    #pragma unroll
    for (int o = 16; o; o >>= 1) v = fmaxf(v, __shfl_xor_sync(0xffffffffu, v, o));
    if (lane == 0) red[wid] = v;
    __syncthreads();
    if (wid == 0) {
        float u = (lane < 8) ? red[lane] : -3.4e38f;
        #pragma unroll
        for (int o = 4; o; o >>= 1) u = fmaxf(u, __shfl_xor_sync(0xffffffffu, u, o));
        if (lane == 0) red[0] = u;
    }
    __syncthreads();
    float r = red[0];
    __syncthreads();
    return r;
}

__device__ __forceinline__ float block_reduce_sum(float v, float* red) {
    int lane = threadIdx.x & 31, wid = threadIdx.x >> 5;
    #pragma unroll
    for (int o = 16; o; o >>= 1) v += __shfl_xor_sync(0xffffffffu, v, o);
    if (lane == 0) red[wid] = v;
    __syncthreads();
    if (wid == 0) {
        float u = (lane < 8) ? red[lane] : 0.f;
        #pragma unroll
        for (int o = 4; o; o >>= 1) u += __shfl_xor_sync(0xffffffffu, u, o);
        if (lane == 0) red[0] = u;
    }
    __syncthreads();
    float r = red[0];
    __syncthreads();
    return r;
}

// ---------------------------------------------------------------------------
// RMSNorm: one block per token row of D=2048, 256 threads x 8 elems
// ---------------------------------------------------------------------------
__global__ void rmsnorm_kernel(const float* __restrict__ x,
                               const float* __restrict__ g,
                               float* __restrict__ y) {
    __shared__ float red[32];
    long row = blockIdx.x;
    const float* xr = x + row * DD;
    float* yr = y + row * DD;
    int tid = threadIdx.x;

    float4 v0 = *(const float4*)&xr[tid * 4];
    float4 v1 = *(const float4*)&xr[1024 + tid * 4];
    float ss = v0.x*v0.x + v0.y*v0.y + v0.z*v0.z + v0.w*v0.w
             + v1.x*v1.x + v1.y*v1.y + v1.z*v1.z + v1.w*v1.w;
    ss = block_reduce_sum(ss, red);
    float norm = rsqrtf(ss * (1.0f / DD) + 1e-6f);

    float4 g0 = *(const float4*)&g[tid * 4];
    float4 g1 = *(const float4*)&g[1024 + tid * 4];
    float4 o0, o1;
    o0.x = v0.x * norm * g0.x; o0.y = v0.y * norm * g0.y;
    o0.z = v0.z * norm * g0.z; o0.w = v0.w * norm * g0.w;
    o1.x = v1.x * norm * g1.x; o1.y = v1.y * norm * g1.y;
    o1.z = v1.z * norm * g1.z; o1.w = v1.w * norm * g1.w;
    *(float4*)&yr[tid * 4] = o0;
    *(float4*)&yr[1024 + tid * 4] = o1;
}

// ---------------------------------------------------------------------------
// Row softmax over rows of length L=2048 (scores already scaled)
// ---------------------------------------------------------------------------
__global__ void softmax_kernel(float* __restrict__ S) {
    __shared__ float red[32];
    long row = blockIdx.x;
    float* p = S + row * (long)LL;
    int tid = threadIdx.x;

    float4 v0 = *(const float4*)&p[tid * 4];
    float4 v1 = *(const float4*)&p[1024 + tid * 4];
    float m = fmaxf(fmaxf(fmaxf(v0.x, v0.y), fmaxf(v0.z, v0.w)),
                    fmaxf(fmaxf(v1.x, v1.y), fmaxf(v1.z, v1.w)));
    m = block_reduce_max(m, red);

    v0.x = __expf(v0.x - m); v0.y = __expf(v0.y - m);
    v0.z = __expf(v0.z - m); v0.w = __expf(v0.w - m);
    v1.x = __expf(v1.x - m); v1.y = __expf(v1.y - m);
    v1.z = __expf(v1.z - m); v1.w = __expf(v1.w - m);

    float s = v0.x + v0.y + v0.z + v0.w + v1.x + v1.y + v1.z + v1.w;
    s = block_reduce_sum(s, red);
    float inv = 1.0f / s;

    v0.x *= inv; v0.y *= inv; v0.z *= inv; v0.w *= inv;
    v1.x *= inv; v1.y *= inv; v1.z *= inv; v1.w *= inv;
    *(float4*)&p[tid * 4] = v0;
    *(float4*)&p[1024 + tid * 4] = v1;
}

// ---------------------------------------------------------------------------
// Generic fp32 GEMM:
//   TB=true : C = epi( A[M,K] * W[N,K]^T )   (NT, both K-major)
//   TB=false: C = epi( A[M,K] * B[K,N] )     (NN)
// 128x128 block tile, BK=16, 256 threads, 8x8 per-thread microtile.
// Batched over blockIdx.z with (b = z/zH, h = z%zH) pointer offsets.
// Epilogue: v = acc*scale; if(mulp) v*=mulp; if(relu) max(v,0); if(addp) v+=addp
// ---------------------------------------------------------------------------
template<bool TB>
__global__ __launch_bounds__(256, 2)
void gemm_kernel(const float* __restrict__ A, const float* __restrict__ Bm,
                 float* __restrict__ C,
                 int K, int lda, int ldb, int ldc,
                 int zH,
                 long sAb, long sAh, long sBb, long sBh, long sCb, long sCh,
                 float scale,
                 const float* __restrict__ mulp,
                 const float* __restrict__ addp,
                 int relu) {
    __shared__ float As[16][128];
    __shared__ float Bs[16][128];

    int z = blockIdx.z;
    int zb = z / zH, zh = z % zH;
    A  += zb * sAb + zh * sAh;
    Bm += zb * sBb + zh * sBh;
    C  += zb * sCb + zh * sCh;
    const float* mp = mulp ? (mulp + zb * sCb + zh * sCh) : nullptr;
    const float* ap = addp ? (addp + zb * sCb + zh * sCh) : nullptr;

    int tid = threadIdx.x;
    int tx = tid & 15;     // col group 0..15
    int ty = tid >> 4;     // row group 0..15
    int row0 = blockIdx.y * 128;
    int col0 = blockIdx.x * 128;

    float acc[8][8];
    #pragma unroll
    for (int i = 0; i < 8; i++)
        #pragma unroll
        for (int j = 0; j < 8; j++) acc[i][j] = 0.f;

    for (int k0 = 0; k0 < K; k0 += 16) {
        // stage A tile (transposed into As[k][m])
        #pragma unroll
        for (int t = 0; t < 2; t++) {
            int q = tid + t * 256;
            int r = q >> 2;
            int kq = (q & 3) * 4;
            float4 v = *(const float4*)&A[(long)(row0 + r) * lda + k0 + kq];
            As[kq + 0][r] = v.x; As[kq + 1][r] = v.y;
            As[kq + 2][r] = v.z; As[kq + 3][r] = v.w;
        }
        if (TB) {
            #pragma unroll
            for (int t = 0; t < 2; t++) {
                int q = tid + t * 256;
                int r = q >> 2;
                int kq = (q & 3) * 4;
                float4 v = *(const float4*)&Bm[(long)(col0 + r) * ldb + k0 + kq];
                Bs[kq + 0][r] = v.x; Bs[kq + 1][r] = v.y;
                Bs[kq + 2][r] = v.z; Bs[kq + 3][r] = v.w;
            }
        } else {
            #pragma unroll
            for (int t = 0; t < 2; t++) {
                int q = tid + t * 256;
                int r = q >> 5;          // k row 0..15
                int cq = (q & 31) * 4;   // col
                *(float4*)&Bs[r][cq] = *(const float4*)&Bm[(long)(k0 + r) * ldb + col0 + cq];
            }
        }
        __syncthreads();

        #pragma unroll
        for (int k = 0; k < 16; k++) {
            float4 a0 = *(const float4*)&As[k][ty * 4];
            float4 a1 = *(const float4*)&As[k][64 + ty * 4];
            float4 b0 = *(const float4*)&Bs[k][tx * 4];
            float4 b1 = *(const float4*)&Bs[k][64 + tx * 4];
            float ar[8] = {a0.x, a0.y, a0.z, a0.w, a1.x, a1.y, a1.z, a1.w};
            float br[8] = {b0.x, b0.y, b0.z, b0.w, b1.x, b1.y, b1.z, b1.w};
            #pragma unroll
            for (int i = 0; i < 8; i++)
                #pragma unroll
                for (int j = 0; j < 8; j++)
                    acc[i][j] += ar[i] * br[j];
        }
        __syncthreads();
    }

    // epilogue (vectorized float4 per 4 cols)
    #pragma unroll
    for (int ib = 0; ib < 2; ib++)
        #pragma unroll
        for (int i = 0; i < 4; i++) {
            int r = row0 + ib * 64 + ty * 4 + i;
            #pragma unroll
            for (int jb = 0; jb < 2; jb++) {
                int c = col0 + jb * 64 + tx * 4;
                long idx = (long)r * ldc + c;
                float4 v;
                v.x = acc[ib * 4 + i][jb * 4 + 0] * scale;
                v.y = acc[ib * 4 + i][jb * 4 + 1] * scale;
                v.z = acc[ib * 4 + i][jb * 4 + 2] * scale;
                v.w = acc[ib * 4 + i][jb * 4 + 3] * scale;
                if (mp) {
                    float4 m4 = *(const float4*)&mp[idx];
                    v.x *= m4.x; v.y *= m4.y; v.z *= m4.z; v.w *= m4.w;
                }
                if (relu) {
                    v.x = fmaxf(v.x, 0.f); v.y = fmaxf(v.y, 0.f);
                    v.z = fmaxf(v.z, 0.f); v.w = fmaxf(v.w, 0.f);
                }
                if (ap) {
                    float4 a4 = *(const float4*)&ap[idx];
                    v.x += a4.x; v.y += a4.y; v.z += a4.z; v.w += a4.w;
                }
                *(float4*)&C[idx] = v;
            }
        }
}

// ---------------------------------------------------------------------------
extern "C" void kernel_launch(void* const* d_in, const int* in_sizes, int n_in,
                              void* d_out, int out_size) {
    (void)in_sizes; (void)n_in; (void)out_size;
    const float* x       = (const float*)d_in[0];
    const float* w_qkv   = (const float*)d_in[1];
    const float* w_out   = (const float*)d_in[2];
    const float* w_in    = (const float*)d_in[3];
    const float* w_hid   = (const float*)d_in[4];
    const float* w_gate  = (const float*)d_in[5];
    const float* g_attng = (const float*)d_in[6];
    const float* g_ffng  = (const float*)d_in[7];
    float* out = (float*)d_out;
    float* scores = out + OUT_ELEMS;

    float *p_xn, *p_qkv, *p_attn, *p_after, *p_yn, *p_hidden, *p_hg;
    cudaGetSymbolAddress((void**)&p_xn, g_xn);
    cudaGetSymbolAddress((void**)&p_qkv, g_qkv);
    cudaGetSymbolAddress((void**)&p_attn, g_attn);
    cudaGetSymbolAddress((void**)&p_after, g_after);
    cudaGetSymbolAddress((void**)&p_yn, g_yn);
    cudaGetSymbolAddress((void**)&p_hidden, g_hidden);
    cudaGetSymbolAddress((void**)&p_hg, g_hg);

    const long sQb = (long)LL * QKVN;  // batch stride inside qkv
    const long sSb = (long)HH * LL * LL;
    const long sSh = (long)LL * LL;
    const float iscale = 0.08838834764831845f;  // 1/sqrt(128)

    // 1) attn-branch RMSNorm
    rmsnorm_kernel<<<TT, 256>>>(x, g_attng, p_xn);

    // 2) QKV GEMM: [4096,2048] x [6144,2048]^T
    gemm_kernel<true><<<dim3(QKVN / 128, TT / 128, 1), 256>>>(
        p_xn, w_qkv, p_qkv, DD, DD, DD, QKVN,
        1, 0, 0, 0, 0, 0, 0, 1.0f, nullptr, nullptr, 0);

    // 3) S = Q K^T / sqrt(HD), per (b,h): M=N=2048, K=128
    gemm_kernel<true><<<dim3(LL / 128, LL / 128, BB * HH), 256>>>(
        p_qkv, p_qkv + DD, scores, HD, QKVN, QKVN, LL,
        HH, sQb, HD, sQb, HD, sSb, sSh, iscale, nullptr, nullptr, 0);

    // 4) row softmax on scores (in place, also the required output)
    softmax_kernel<<<BB * HH * LL, 256>>>(scores);

    // 5) attn = P V, per (b,h): M=2048, N=128, K=2048 (NN)
    gemm_kernel<false><<<dim3(1, LL / 128, BB * HH), 256>>>(
        scores, p_qkv + 2 * DD, p_attn, LL, LL, QKVN, DD,
        HH, sSb, sSh, sQb, HD, (long)LL * DD, HD, 1.0f, nullptr, nullptr, 0);

    // 6) after_attn = x + attn * w_out^T
    gemm_kernel<true><<<dim3(DD / 128, TT / 128, 1), 256>>>(
        p_attn, w_out, p_after, DD, DD, DD, DD,
        1, 0, 0, 0, 0, 0, 0, 1.0f, nullptr, x, 0);

    // 7) FFN-branch RMSNorm
    rmsnorm_kernel<<<TT, 256>>>(p_after, g_ffng, p_yn);

    // 8) hidden = relu(yn * w_in^T)
    gemm_kernel<true><<<dim3(DD / 128, TT / 128, 1), 256>>>(
        p_yn, w_in, p_hidden, DD, DD, DD, DD,
        1, 0, 0, 0, 0, 0, 0, 1.0f, nullptr, nullptr, 1);

    // 9) hg = hidden * (hidden * w_gate^T)   (gate epilogue multiplies by hidden)
    gemm_kernel<true><<<dim3(DD / 128, TT / 128, 1), 256>>>(
        p_hidden, w_gate, p_hg, DD, DD, DD, DD,
        1, 0, 0, 0, 0, 0, 0, 1.0f, p_hidden, nullptr, 0);

    // 10) out = after_attn + hg * w_hidden^T
    gemm_kernel<true><<<dim3(DD / 128, TT / 128, 1), 256>>>(
        p_hg, w_hid, out, DD, DD, DD, DD,
        1, 0, 0, 0, 0, 0, 0, 1.0f, nullptr, p_after, 0);
}

// round 3
// speedup vs baseline: 2.5970x; 2.5970x over previous
#include <cuda_runtime.h>
#include <cuda_bf16.h>
#include <cstdint>

// Problem constants
#define BB 2
#define LL 2048
#define DD 2048
#define HH 16
#define HD 128
#define TT (BB*LL)            // 4096 tokens
#define QKVN (3*DD)           // 6144
#define OUT_ELEMS ((long)TT*DD)          // 8388608
#define SCORE_ELEMS ((long)BB*HH*LL*LL)  // 134217728

// Scratch (device globals; no allocation allowed)
__device__ float g_xn[TT*DD];
__device__ float g_qkv[TT*QKVN];
__device__ float g_attn[TT*DD];
__device__ float g_after[TT*DD];
__device__ float g_yn[TT*DD];
__device__ float g_hidden[TT*DD];
__device__ float g_hg[TT*DD];

// ---------------------------------------------------------------------------
// Block reductions (256 threads = 8 warps)
// ---------------------------------------------------------------------------
__device__ __forceinline__ float block_reduce_max(float v, float* red) {
    int lane = threadIdx.x & 31, wid = threadIdx.x >> 5;
    #pragma unroll
    for (int o = 16; o; o >>= 1) v = fmaxf(v, __shfl_xor_sync(0xffffffffu, v, o));
    if (lane == 0) red[wid] = v;
    __syncthreads();
    if (wid == 0) {
        float u = (lane < 8) ? red[lane] : -3.4e38f;
        #pragma unroll
        for (int o = 4; o; o >>= 1) u = fmaxf(u, __shfl_xor_sync(0xffffffffu, u, o));
        if (lane == 0) red[0] = u;
    }
    __syncthreads();
    float r = red[0];
    __syncthreads();
    return r;
}

__device__ __forceinline__ float block_reduce_sum(float v, float* red) {
    int lane = threadIdx.x & 31, wid = threadIdx.x >> 5;
    #pragma unroll
    for (int o = 16; o; o >>= 1) v += __shfl_xor_sync(0xffffffffu, v, o);
    if (lane == 0) red[wid] = v;
    __syncthreads();
    if (wid == 0) {
        float u = (lane < 8) ? red[lane] : 0.f;
        #pragma unroll
        for (int o = 4; o; o >>= 1) u += __shfl_xor_sync(0xffffffffu, u, o);
        if (lane == 0) red[0] = u;
    }
    __syncthreads();
    float r = red[0];
    __syncthreads();
    return r;
}

// ---------------------------------------------------------------------------
// RMSNorm: one block per token row of D=2048, 256 threads x 8 elems
// ---------------------------------------------------------------------------
__global__ void rmsnorm_kernel(const float* __restrict__ x,
                               const float* __restrict__ g,
                               float* __restrict__ y) {
    __shared__ float red[32];
    long row = blockIdx.x;
    const float* xr = x + row * DD;
    float* yr = y + row * DD;
    int tid = threadIdx.x;

    float4 v0 = *(const float4*)&xr[tid * 4];
    float4 v1 = *(const float4*)&xr[1024 + tid * 4];
    float ss = v0.x*v0.x + v0.y*v0.y + v0.z*v0.z + v0.w*v0.w
             + v1.x*v1.x + v1.y*v1.y + v1.z*v1.z + v1.w*v1.w;
    ss = block_reduce_sum(ss, red);
    float norm = rsqrtf(ss * (1.0f / DD) + 1e-6f);

    float4 g0 = *(const float4*)&g[tid * 4];
    float4 g1 = *(const float4*)&g[1024 + tid * 4];
    float4 o0, o1;
    o0.x = v0.x * norm * g0.x; o0.y = v0.y * norm * g0.y;
    o0.z = v0.z * norm * g0.z; o0.w = v0.w * norm * g0.w;
    o1.x = v1.x * norm * g1.x; o1.y = v1.y * norm * g1.y;
    o1.z = v1.z * norm * g1.z; o1.w = v1.w * norm * g1.w;
    *(float4*)&yr[tid * 4] = o0;
    *(float4*)&yr[1024 + tid * 4] = o1;
}

// ---------------------------------------------------------------------------
// Row softmax over rows of length L=2048 (already at DRAM roofline)
// ---------------------------------------------------------------------------
__global__ void softmax_kernel(float* __restrict__ S) {
    __shared__ float red[32];
    long row = blockIdx.x;
    float* p = S + row * (long)LL;
    int tid = threadIdx.x;

    float4 v0 = *(const float4*)&p[tid * 4];
    float4 v1 = *(const float4*)&p[1024 + tid * 4];
    float m = fmaxf(fmaxf(fmaxf(v0.x, v0.y), fmaxf(v0.z, v0.w)),
                    fmaxf(fmaxf(v1.x, v1.y), fmaxf(v1.z, v1.w)));
    m = block_reduce_max(m, red);

    v0.x = __expf(v0.x - m); v0.y = __expf(v0.y - m);
    v0.z = __expf(v0.z - m); v0.w = __expf(v0.w - m);
    v1.x = __expf(v1.x - m); v1.y = __expf(v1.y - m);
    v1.z = __expf(v1.z - m); v1.w = __expf(v1.w - m);

    float s = v0.x + v0.y + v0.z + v0.w + v1.x + v1.y + v1.z + v1.w;
    s = block_reduce_sum(s, red);
    float inv = 1.0f / s;

    v0.x *= inv; v0.y *= inv; v0.z *= inv; v0.w *= inv;
    v1.x *= inv; v1.y *= inv; v1.z *= inv; v1.w *= inv;
    *(float4*)&p[tid * 4] = v0;
    *(float4*)&p[1024 + tid * 4] = v1;
}

// ---------------------------------------------------------------------------
// TF32 tensor-core GEMM (mma.sync.m16n8k8.tf32)
//   TB=true : C = epi( A[M,K] * W[N,K]^T )   (NT, both K-major)
//   TB=false: C = epi( A[M,K] * B[K,N] )     (NN)
// Block tile 128x128xBK32, 256 threads = 8 warps (2x4), warp tile 64x32.
// ---------------------------------------------------------------------------
__device__ __forceinline__ uint32_t f2tf32(float f) {
    uint32_t u;
    asm("cvt.rna.tf32.f32 %0, %1;" : "=r"(u) : "f"(f));
    return u;
}

__device__ __forceinline__ void mma_tf32(float* c, uint32_t a0, uint32_t a1,
                                         uint32_t a2, uint32_t a3,
                                         uint32_t b0, uint32_t b1) {
    asm volatile(
        "mma.sync.aligned.m16n8k8.row.col.f32.tf32.tf32.f32 "
        "{%0,%1,%2,%3}, {%4,%5,%6,%7}, {%8,%9}, {%0,%1,%2,%3};"
        : "+f"(c[0]), "+f"(c[1]), "+f"(c[2]), "+f"(c[3])
        : "r"(a0), "r"(a1), "r"(a2), "r"(a3), "r"(b0), "r"(b1));
}

template<bool TB>
__global__ __launch_bounds__(256, 2)
void gemm_tc(const float* __restrict__ A, const float* __restrict__ Bm,
             float* __restrict__ C,
             int K, int lda, int ldb, int ldc,
             int zH,
             long sAb, long sAh, long sBb, long sBh, long sCb, long sCh,
             float scale,
             const float* __restrict__ mulp,
             const float* __restrict__ addp,
             int relu) {
    constexpr int PA = 133;              // conflict-free transposed scalar stores
    constexpr int PB = TB ? 133 : 136;   // NN: aligned uint4 stores + cf frag reads
    __shared__ uint32_t As[32 * PA];
    __shared__ uint32_t Bs[32 * PB];

    int z = blockIdx.z;
    int zb = z / zH, zh = z % zH;
    A  += zb * sAb + zh * sAh;
    Bm += zb * sBb + zh * sBh;
    C  += zb * sCb + zh * sCh;
    const float* mp = mulp ? (mulp + zb * sCb + zh * sCh) : nullptr;
    const float* ap = addp ? (addp + zb * sCb + zh * sCh) : nullptr;

    int tid = threadIdx.x;
    int lane = tid & 31, warp = tid >> 5;
    int wm = warp >> 2;         // 0..1
    int wn = warp & 3;          // 0..3
    int g = lane >> 2, tig = lane & 3;
    int m_base = wm * 64, n_base = wn * 32;
    int row0 = blockIdx.y * 128;
    int col0 = blockIdx.x * 128;

    float acc[4][4][4];
    #pragma unroll
    for (int mi = 0; mi < 4; mi++)
        #pragma unroll
        for (int ni = 0; ni < 4; ni++)
            #pragma unroll
            for (int r = 0; r < 4; r++) acc[mi][ni][r] = 0.f;

    for (int k0 = 0; k0 < K; k0 += 32) {
        // --- stage A (always transposed into As[k][m]) ---
        #pragma unroll
        for (int t = 0; t < 4; t++) {
            int q = tid + t * 256;
            int r = q >> 3;             // 0..127 (m)
            int kq = (q & 7) * 4;       // 0..28  (k)
            float4 v = *(const float4*)&A[(long)(row0 + r) * lda + k0 + kq];
            As[(kq + 0) * PA + r] = f2tf32(v.x);
            As[(kq + 1) * PA + r] = f2tf32(v.y);
            As[(kq + 2) * PA + r] = f2tf32(v.z);
            As[(kq + 3) * PA + r] = f2tf32(v.w);
        }
        // --- stage B ---
        if (TB) {
            #pragma unroll
            for (int t = 0; t < 4; t++) {
                int q = tid + t * 256;
                int r = q >> 3;             // 0..127 (n)
                int kq = (q & 7) * 4;
                float4 v = *(const float4*)&Bm[(long)(col0 + r) * ldb + k0 + kq];
                Bs[(kq + 0) * PB + r] = f2tf32(v.x);
                Bs[(kq + 1) * PB + r] = f2tf32(v.y);
                Bs[(kq + 2) * PB + r] = f2tf32(v.z);
                Bs[(kq + 3) * PB + r] = f2tf32(v.w);
            }
        } else {
            #pragma unroll
            for (int t = 0; t < 4; t++) {
                int q = tid + t * 256;
                int r = q >> 5;             // 0..31 (k)
                int c = (q & 31) * 4;       // 0..124 (n)
                float4 v = *(const float4*)&Bm[(long)(k0 + r) * ldb + col0 + c];
                uint4 u;
                u.x = f2tf32(v.x); u.y = f2tf32(v.y);
                u.z = f2tf32(v.z); u.w = f2tf32(v.w);
                *(uint4*)&Bs[r * PB + c] = u;
            }
        }
        __syncthreads();

        // --- compute: 4 k-steps of 8 ---
        #pragma unroll
        for (int kk = 0; kk < 32; kk += 8) {
            uint32_t af[4][4], bf[4][2];
            #pragma unroll
            for (int mi = 0; mi < 4; mi++) {
                int mr = m_base + mi * 16 + g;
                af[mi][0] = As[(kk + tig) * PA + mr];
                af[mi][1] = As[(kk + tig) * PA + mr + 8];
                af[mi][2] = As[(kk + tig + 4) * PA + mr];
                af[mi][3] = As[(kk + tig + 4) * PA + mr + 8];
            }
            #pragma unroll
            for (int ni = 0; ni < 4; ni++) {
                int nc = n_base + ni * 8 + g;
                bf[ni][0] = Bs[(kk + tig) * PB + nc];
                bf[ni][1] = Bs[(kk + tig + 4) * PB + nc];
            }
            #pragma unroll
            for (int mi = 0; mi < 4; mi++)
                #pragma unroll
                for (int ni = 0; ni < 4; ni++)
                    mma_tf32(acc[mi][ni], af[mi][0], af[mi][1], af[mi][2],
                             af[mi][3], bf[ni][0], bf[ni][1]);
        }
        __syncthreads();
    }

    // --- epilogue ---
    #pragma unroll
    for (int mi = 0; mi < 4; mi++) {
        #pragma unroll
        for (int half = 0; half < 2; half++) {
            int r = row0 + m_base + mi * 16 + g + half * 8;
            #pragma unroll
            for (int ni = 0; ni < 4; ni++) {
                int c = col0 + n_base + ni * 8 + tig * 2;
                long idx = (long)r * ldc + c;
                float2 v;
                v.x = acc[mi][ni][half * 2 + 0] * scale;
                v.y = acc[mi][ni][half * 2 + 1] * scale;
                if (mp) {
                    float2 m2 = *(const float2*)&mp[idx];
                    v.x *= m2.x; v.y *= m2.y;
                }
                if (relu) { v.x = fmaxf(v.x, 0.f); v.y = fmaxf(v.y, 0.f); }
                if (ap) {
                    float2 a2 = *(const float2*)&ap[idx];
                    v.x += a2.x; v.y += a2.y;
                }
                *(float2*)&C[idx] = v;
            }
        }
    }
}

// ---------------------------------------------------------------------------
extern "C" void kernel_launch(void* const* d_in, const int* in_sizes, int n_in,
                              void* d_out, int out_size) {
    (void)in_sizes; (void)n_in; (void)out_size;
    const float* x       = (const float*)d_in[0];
    const float* w_qkv   = (const float*)d_in[1];
    const float* w_out   = (const float*)d_in[2];
    const float* w_in    = (const float*)d_in[3];
    const float* w_hid   = (const float*)d_in[4];
    const float* w_gate  = (const float*)d_in[5];
    const float* g_attng = (const float*)d_in[6];
    const float* g_ffng  = (const float*)d_in[7];
    float* out = (float*)d_out;
    float* scores = out + OUT_ELEMS;

    float *p_xn, *p_qkv, *p_attn, *p_after, *p_yn, *p_hidden, *p_hg;
    cudaGetSymbolAddress((void**)&p_xn, g_xn);
    cudaGetSymbolAddress((void**)&p_qkv, g_qkv);
    cudaGetSymbolAddress((void**)&p_attn, g_attn);
    cudaGetSymbolAddress((void**)&p_after, g_after);
    cudaGetSymbolAddress((void**)&p_yn, g_yn);
    cudaGetSymbolAddress((void**)&p_hidden, g_hidden);
    cudaGetSymbolAddress((void**)&p_hg, g_hg);

    const long sQb = (long)LL * QKVN;  // batch stride inside qkv
    const long sSb = (long)HH * LL * LL;
    const long sSh = (long)LL * LL;
    const float iscale = 0.08838834764831845f;  // 1/sqrt(128)

    // 1) attn-branch RMSNorm
    rmsnorm_kernel<<<TT, 256>>>(x, g_attng, p_xn);

    // 2) QKV GEMM: [4096,2048] x [6144,2048]^T
    gemm_tc<true><<<dim3(QKVN / 128, TT / 128, 1), 256>>>(
        p_xn, w_qkv, p_qkv, DD, DD, DD, QKVN,
        1, 0, 0, 0, 0, 0, 0, 1.0f, nullptr, nullptr, 0);

    // 3) S = Q K^T / sqrt(HD), per (b,h): M=N=2048, K=128
    gemm_tc<true><<<dim3(LL / 128, LL / 128, BB * HH), 256>>>(
        p_qkv, p_qkv + DD, scores, HD, QKVN, QKVN, LL,
        HH, sQb, HD, sQb, HD, sSb, sSh, iscale, nullptr, nullptr, 0);

    // 4) row softmax on scores (in place, also the required output)
    softmax_kernel<<<BB * HH * LL, 256>>>(scores);

    // 5) attn = P V, per (b,h): M=2048, N=128, K=2048 (NN)
    gemm_tc<false><<<dim3(1, LL / 128, BB * HH), 256>>>(
        scores, p_qkv + 2 * DD, p_attn, LL, LL, QKVN, DD,
        HH, sSb, sSh, sQb, HD, (long)LL * DD, HD, 1.0f, nullptr, nullptr, 0);

    // 6) after_attn = x + attn * w_out^T
    gemm_tc<true><<<dim3(DD / 128, TT / 128, 1), 256>>>(
        p_attn, w_out, p_after, DD, DD, DD, DD,
        1, 0, 0, 0, 0, 0, 0, 1.0f, nullptr, x, 0);

    // 7) FFN-branch RMSNorm
    rmsnorm_kernel<<<TT, 256>>>(p_after, g_ffng, p_yn);

    // 8) hidden = relu(yn * w_in^T)
    gemm_tc<true><<<dim3(DD / 128, TT / 128, 1), 256>>>(
        p_yn, w_in, p_hidden, DD, DD, DD, DD,
        1, 0, 0, 0, 0, 0, 0, 1.0f, nullptr, nullptr, 1);

    // 9) hg = hidden * (hidden * w_gate^T)   (gate epilogue multiplies by hidden)
    gemm_tc<true><<<dim3(DD / 128, TT / 128, 1), 256>>>(
        p_hidden, w_gate, p_hg, DD, DD, DD, DD,
        1, 0, 0, 0, 0, 0, 0, 1.0f, p_hidden, nullptr, 0);

    // 10) out = after_attn + hg * w_hidden^T
    gemm_tc<true><<<dim3(DD / 128, TT / 128, 1), 256>>>(
        p_hg, w_hid, out, DD, DD, DD, DD,
        1, 0, 0, 0, 0, 0, 0, 1.0f, nullptr, p_after, 0);
}

// round 6
// speedup vs baseline: 3.2870x; 1.2657x over previous
#include <cuda_runtime.h>
#include <cuda_bf16.h>
#include <cstdint>

// Problem constants
#define BB 2
#define LL 2048
#define DD 2048
#define HH 16
#define HD 128
#define TT (BB*LL)            // 4096 tokens
#define QKVN (3*DD)           // 6144
#define OUT_ELEMS ((long)TT*DD)          // 8388608
#define SCORE_ELEMS ((long)BB*HH*LL*LL)  // 134217728

// Scratch (device globals; no allocation allowed)
__device__ float g_xn[TT*DD];
__device__ float g_qkv[TT*QKVN];
__device__ float g_attn[TT*DD];
__device__ float g_after[TT*DD];
__device__ float g_yn[TT*DD];
__device__ float g_hidden[TT*DD];
__device__ float g_hg[TT*DD];

// ---------------------------------------------------------------------------
// Block reductions (256 threads = 8 warps)
// ---------------------------------------------------------------------------
__device__ __forceinline__ float block_reduce_max(float v, float* red) {
    int lane = threadIdx.x & 31, wid = threadIdx.x >> 5;
    #pragma unroll
    for (int o = 16; o; o >>= 1) v = fmaxf(v, __shfl_xor_sync(0xffffffffu, v, o));
    if (lane == 0) red[wid] = v;
    __syncthreads();
    if (wid == 0) {
        float u = (lane < 8) ? red[lane] : -3.4e38f;
        #pragma unroll
        for (int o = 4; o; o >>= 1) u = fmaxf(u, __shfl_xor_sync(0xffffffffu, u, o));
        if (lane == 0) red[0] = u;
    }
    __syncthreads();
    float r = red[0];
    __syncthreads();
    return r;
}

__device__ __forceinline__ float block_reduce_sum(float v, float* red) {
    int lane = threadIdx.x & 31, wid = threadIdx.x >> 5;
    #pragma unroll
    for (int o = 16; o; o >>= 1) v += __shfl_xor_sync(0xffffffffu, v, o);
    if (lane == 0) red[wid] = v;
    __syncthreads();
    if (wid == 0) {
        float u = (lane < 8) ? red[lane] : 0.f;
        #pragma unroll
        for (int o = 4; o; o >>= 1) u += __shfl_xor_sync(0xffffffffu, u, o);
        if (lane == 0) red[0] = u;
    }
    __syncthreads();
    float r = red[0];
    __syncthreads();
    return r;
}

// ---------------------------------------------------------------------------
// RMSNorm: one block per token row of D=2048, 256 threads x 8 elems
// ---------------------------------------------------------------------------
__global__ void rmsnorm_kernel(const float* __restrict__ x,
                               const float* __restrict__ g,
                               float* __restrict__ y) {
    __shared__ float red[32];
    long row = blockIdx.x;
    const float* xr = x + row * DD;
    float* yr = y + row * DD;
    int tid = threadIdx.x;

    float4 v0 = *(const float4*)&xr[tid * 4];
    float4 v1 = *(const float4*)&xr[1024 + tid * 4];
    float ss = v0.x*v0.x + v0.y*v0.y + v0.z*v0.z + v0.w*v0.w
             + v1.x*v1.x + v1.y*v1.y + v1.z*v1.z + v1.w*v1.w;
    ss = block_reduce_sum(ss, red);
    float norm = rsqrtf(ss * (1.0f / DD) + 1e-6f);

    float4 g0 = *(const float4*)&g[tid * 4];
    float4 g1 = *(const float4*)&g[1024 + tid * 4];
    float4 o0, o1;
    o0.x = v0.x * norm * g0.x; o0.y = v0.y * norm * g0.y;
    o0.z = v0.z * norm * g0.z; o0.w = v0.w * norm * g0.w;
    o1.x = v1.x * norm * g1.x; o1.y = v1.y * norm * g1.y;
    o1.z = v1.z * norm * g1.z; o1.w = v1.w * norm * g1.w;
    *(float4*)&yr[tid * 4] = o0;
    *(float4*)&yr[1024 + tid * 4] = o1;
}

// ---------------------------------------------------------------------------
// Row softmax over rows of length L=2048 (already at DRAM roofline)
// ---------------------------------------------------------------------------
__global__ void softmax_kernel(float* __restrict__ S) {
    __shared__ float red[32];
    long row = blockIdx.x;
    float* p = S + row * (long)LL;
    int tid = threadIdx.x;

    float4 v0 = *(const float4*)&p[tid * 4];
    float4 v1 = *(const float4*)&p[1024 + tid * 4];
    float m = fmaxf(fmaxf(fmaxf(v0.x, v0.y), fmaxf(v0.z, v0.w)),
                    fmaxf(fmaxf(v1.x, v1.y), fmaxf(v1.z, v1.w)));
    m = block_reduce_max(m, red);

    v0.x = __expf(v0.x - m); v0.y = __expf(v0.y - m);
    v0.z = __expf(v0.z - m); v0.w = __expf(v0.w - m);
    v1.x = __expf(v1.x - m); v1.y = __expf(v1.y - m);
    v1.z = __expf(v1.z - m); v1.w = __expf(v1.w - m);

    float s = v0.x + v0.y + v0.z + v0.w + v1.x + v1.y + v1.z + v1.w;
    s = block_reduce_sum(s, red);
    float inv = 1.0f / s;

    v0.x *= inv; v0.y *= inv; v0.z *= inv; v0.w *= inv;
    v1.x *= inv; v1.y *= inv; v1.z *= inv; v1.w *= inv;
    *(float4*)&p[tid * 4] = v0;
    *(float4*)&p[1024 + tid * 4] = v1;
}

// ---------------------------------------------------------------------------
// TF32 tensor-core GEMM with cp.async double buffering.
//   TB=true : C = epi( A[M,K] * W[N,K]^T )   (NT, both K-major)
//   TB=false: C = epi( A[M,K] * B[K,N] )     (NN)
// Block tile 128x128x32, 256 threads = 8 warps (2x4), warp tile 64x32.
// smem holds raw fp32 (cp.async), cvt.rna.tf32 applied at fragment load.
// Layouts: A [m][k] pad36 (bank=(4g+tig)%32 distinct); B-NT same;
//          B-NN [k][n] pad136 (bank=(8tig+g)%32 distinct).
// ---------------------------------------------------------------------------
__device__ __forceinline__ uint32_t f2tf32(float f) {
    uint32_t u;
    asm("cvt.rna.tf32.f32 %0, %1;" : "=r"(u) : "f"(f));
    return u;
}

__device__ __forceinline__ void cp16(float* smem_dst, const float* gmem_src) {
    uint32_t d = (uint32_t)__cvta_generic_to_shared(smem_dst);
    asm volatile("cp.async.cg.shared.global [%0], [%1], 16;\n"
                 :: "r"(d), "l"(gmem_src));
}

__device__ __forceinline__ void mma_tf32(float* c, uint32_t a0, uint32_t a1,
                                         uint32_t a2, uint32_t a3,
                                         uint32_t b0, uint32_t b1) {
    asm volatile(
        "mma.sync.aligned.m16n8k8.row.col.f32.tf32.tf32.f32 "
        "{%0,%1,%2,%3}, {%4,%5,%6,%7}, {%8,%9}, {%0,%1,%2,%3};"
        : "+f"(c[0]), "+f"(c[1]), "+f"(c[2]), "+f"(c[3])
        : "r"(a0), "r"(a1), "r"(a2), "r"(a3), "r"(b0), "r"(b1));
}

template<bool TB>
__global__ __launch_bounds__(256, 2)
void gemm_tc(const float* __restrict__ A, const float* __restrict__ Bm,
             float* __restrict__ C,
             int K, int lda, int ldb, int ldc,
             int zH,
             long sAb, long sAh, long sBb, long sBh, long sCb, long sCh,
             float scale,
             const float* __restrict__ mulp,
             const float* __restrict__ addp,
             int relu) {
    constexpr int PA = 36;                     // floats per A row (m-major)
    constexpr int ASZ = 128 * PA;              // one A buffer
    constexpr int PBNN = 136;                  // floats per B row (k-major, NN)
    constexpr int BSZ = TB ? 128 * PA : 32 * PBNN;

    extern __shared__ float smem[];
    float* As = smem;                  // 2 buffers
    float* Bs = smem + 2 * ASZ;        // 2 buffers

    int z = blockIdx.z;
    int zb = z / zH, zh = z % zH;
    A  += zb * sAb + zh * sAh;
    Bm += zb * sBb + zh * sBh;
    C  += zb * sCb + zh * sCh;
    const float* mp = mulp ? (mulp + zb * sCb + zh * sCh) : nullptr;
    const float* ap = addp ? (addp + zb * sCb + zh * sCh) : nullptr;

    int tid = threadIdx.x;
    int lane = tid & 31, warp = tid >> 5;
    int wm = warp >> 2;         // 0..1
    int wn = warp & 3;          // 0..3
    int g = lane >> 2, tig = lane & 3;
    int m_base = wm * 64, n_base = wn * 32;
    int row0 = blockIdx.y * 128;
    int col0 = blockIdx.x * 128;

    float acc[4][4][4];
    #pragma unroll
    for (int mi = 0; mi < 4; mi++)
        #pragma unroll
        for (int ni = 0; ni < 4; ni++)
            #pragma unroll
            for (int r = 0; r < 4; r++) acc[mi][ni][r] = 0.f;

    // stage-issue helpers
    int ar = tid >> 3;              // 0..31 used as m (A) / n (B-NT) base row
    int akq = (tid & 7) * 4;        // k offset within 32
    int br_nn = tid >> 6;           // 0..3 k-row group for NN
    int bc_nn = (tid & 63) * 4;     // 0..252 -> but cols only 128: use t loop

    auto issue_tile = [&](int k0, int buf) {
        float* Ab = As + buf * ASZ;
        #pragma unroll
        for (int t = 0; t < 4; t++) {
            int r = ar + t * 32;
            cp16(&Ab[r * PA + akq], &A[(long)(row0 + r) * lda + k0 + akq]);
        }
        float* Bb = Bs + buf * BSZ;
        if (TB) {
            #pragma unroll
            for (int t = 0; t < 4; t++) {
                int r = ar + t * 32;
                cp16(&Bb[r * PA + akq], &Bm[(long)(col0 + r) * ldb + k0 + akq]);
            }
        } else {
            #pragma unroll
            for (int t = 0; t < 4; t++) {
                int q = tid + t * 256;
                int r = q >> 5;             // k row 0..31
                int c = (q & 31) * 4;       // col 0..124
                cp16(&Bb[r * PBNN + c], &Bm[(long)(k0 + r) * ldb + col0 + c]);
            }
        }
        asm volatile("cp.async.commit_group;\n" ::);
    };

    int nk = K >> 5;
    issue_tile(0, 0);

    for (int i = 0; i < nk; i++) {
        if (i + 1 < nk) {
            issue_tile((i + 1) << 5, (i + 1) & 1);
            asm volatile("cp.async.wait_group 1;\n" ::);
        } else {
            asm volatile("cp.async.wait_group 0;\n" ::);
        }
        __syncthreads();

        const float* Ab = As + (i & 1) * ASZ;
        const float* Bb = Bs + (i & 1) * BSZ;

        #pragma unroll
        for (int kk = 0; kk < 32; kk += 8) {
            uint32_t af[4][4], bf[4][2];
            #pragma unroll
            for (int mi = 0; mi < 4; mi++) {
                int mr = m_base + mi * 16 + g;
                af[mi][0] = f2tf32(Ab[mr * PA + kk + tig]);
                af[mi][1] = f2tf32(Ab[(mr + 8) * PA + kk + tig]);
                af[mi][2] = f2tf32(Ab[mr * PA + kk + tig + 4]);
                af[mi][3] = f2tf32(Ab[(mr + 8) * PA + kk + tig + 4]);
            }
            #pragma unroll
            for (int ni = 0; ni < 4; ni++) {
                int nc = n_base + ni * 8 + g;
                if (TB) {
                    bf[ni][0] = f2tf32(Bb[nc * PA + kk + tig]);
                    bf[ni][1] = f2tf32(Bb[nc * PA + kk + tig + 4]);
                } else {
                    bf[ni][0] = f2tf32(Bb[(kk + tig) * PBNN + nc]);
                    bf[ni][1] = f2tf32(Bb[(kk + tig + 4) * PBNN + nc]);
                }
            }
            #pragma unroll
            for (int mi = 0; mi < 4; mi++)
                #pragma unroll
                for (int ni = 0; ni < 4; ni++)
                    mma_tf32(acc[mi][ni], af[mi][0], af[mi][1], af[mi][2],
                             af[mi][3], bf[ni][0], bf[ni][1]);
        }
        __syncthreads();
    }

    // --- epilogue ---
    #pragma unroll
    for (int mi = 0; mi < 4; mi++) {
        #pragma unroll
        for (int half = 0; half < 2; half++) {
            int r = row0 + m_base + mi * 16 + g + half * 8;
            #pragma unroll
            for (int ni = 0; ni < 4; ni++) {
                int c = col0 + n_base + ni * 8 + tig * 2;
                long idx = (long)r * ldc + c;
                float2 v;
                v.x = acc[mi][ni][half * 2 + 0] * scale;
                v.y = acc[mi][ni][half * 2 + 1] * scale;
                if (mp) {
                    float2 m2 = *(const float2*)&mp[idx];
                    v.x *= m2.x; v.y *= m2.y;
                }
                if (relu) { v.x = fmaxf(v.x, 0.f); v.y = fmaxf(v.y, 0.f); }
                if (ap) {
                    float2 a2 = *(const float2*)&ap[idx];
                    v.x += a2.x; v.y += a2.y;
                }
                *(float2*)&C[idx] = v;
            }
        }
    }
}

// ---------------------------------------------------------------------------
extern "C" void kernel_launch(void* const* d_in, const int* in_sizes, int n_in,
                              void* d_out, int out_size) {
    (void)in_sizes; (void)n_in; (void)out_size;
    const float* x       = (const float*)d_in[0];
    const float* w_qkv   = (const float*)d_in[1];
    const float* w_out   = (const float*)d_in[2];
    const float* w_in    = (const float*)d_in[3];
    const float* w_hid   = (const float*)d_in[4];
    const float* w_gate  = (const float*)d_in[5];
    const float* g_attng = (const float*)d_in[6];
    const float* g_ffng  = (const float*)d_in[7];
    float* out = (float*)d_out;
    float* scores = out + OUT_ELEMS;

    float *p_xn, *p_qkv, *p_attn, *p_after, *p_yn, *p_hidden, *p_hg;
    cudaGetSymbolAddress((void**)&p_xn, g_xn);
    cudaGetSymbolAddress((void**)&p_qkv, g_qkv);
    cudaGetSymbolAddress((void**)&p_attn, g_attn);
    cudaGetSymbolAddress((void**)&p_after, g_after);
    cudaGetSymbolAddress((void**)&p_yn, g_yn);
    cudaGetSymbolAddress((void**)&p_hidden, g_hidden);
    cudaGetSymbolAddress((void**)&p_hg, g_hg);

    const int SMEM_NT = (2 * 128 * 36 + 2 * 128 * 36) * 4;   // 73728
    const int SMEM_NN = (2 * 128 * 36 + 2 * 32 * 136) * 4;   // 71680
    static int attr_done = 0;
    if (!attr_done) {
        cudaFuncSetAttribute(gemm_tc<true>,
            cudaFuncAttributeMaxDynamicSharedMemorySize, SMEM_NT);
        cudaFuncSetAttribute(gemm_tc<false>,
            cudaFuncAttributeMaxDynamicSharedMemorySize, SMEM_NN);
        attr_done = 1;
    }

    const long sQb = (long)LL * QKVN;  // batch stride inside qkv
    const long sSb = (long)HH * LL * LL;
    const long sSh = (long)LL * LL;
    const float iscale = 0.08838834764831845f;  // 1/sqrt(128)

    // 1) attn-branch RMSNorm
    rmsnorm_kernel<<<TT, 256>>>(x, g_attng, p_xn);

    // 2) QKV GEMM: [4096,2048] x [6144,2048]^T
    gemm_tc<true><<<dim3(QKVN / 128, TT / 128, 1), 256, SMEM_NT>>>(
        p_xn, w_qkv, p_qkv, DD, DD, DD, QKVN,
        1, 0, 0, 0, 0, 0, 0, 1.0f, nullptr, nullptr, 0);

    // 3) S = Q K^T / sqrt(HD), per (b,h): M=N=2048, K=128
    gemm_tc<true><<<dim3(LL / 128, LL / 128, BB * HH), 256, SMEM_NT>>>(
        p_qkv, p_qkv + DD, scores, HD, QKVN, QKVN, LL,
        HH, sQb, HD, sQb, HD, sSb, sSh, iscale, nullptr, nullptr, 0);

    // 4) row softmax on scores (in place, also the required output)
    softmax_kernel<<<BB * HH * LL, 256>>>(scores);

    // 5) attn = P V, per (b,h): M=2048, N=128, K=2048 (NN)
    gemm_tc<false><<<dim3(1, LL / 128, BB * HH), 256, SMEM_NN>>>(
        scores, p_qkv + 2 * DD, p_attn, LL, LL, QKVN, DD,
        HH, sSb, sSh, sQb, HD, (long)LL * DD, HD, 1.0f, nullptr, nullptr, 0);

    // 6) after_attn = x + attn * w_out^T
    gemm_tc<true><<<dim3(DD / 128, TT / 128, 1), 256, SMEM_NT>>>(
        p_attn, w_out, p_after, DD, DD, DD, DD,
        1, 0, 0, 0, 0, 0, 0, 1.0f, nullptr, x, 0);

    // 7) FFN-branch RMSNorm
    rmsnorm_kernel<<<TT, 256>>>(p_after, g_ffng, p_yn);

    // 8) hidden = relu(yn * w_in^T)
    gemm_tc<true><<<dim3(DD / 128, TT / 128, 1), 256, SMEM_NT>>>(
        p_yn, w_in, p_hidden, DD, DD, DD, DD,
        1, 0, 0, 0, 0, 0, 0, 1.0f, nullptr, nullptr, 1);

    // 9) hg = hidden * (hidden * w_gate^T)   (gate epilogue multiplies by hidden)
    gemm_tc<true><<<dim3(DD / 128, TT / 128, 1), 256, SMEM_NT>>>(
        p_hidden, w_gate, p_hg, DD, DD, DD, DD,
        1, 0, 0, 0, 0, 0, 0, 1.0f, p_hidden, nullptr, 0);

    // 10) out = after_attn + hg * w_hidden^T
    gemm_tc<true><<<dim3(DD / 128, TT / 128, 1), 256, SMEM_NT>>>(
        p_hg, w_hid, out, DD, DD, DD, DD,
        1, 0, 0, 0, 0, 0, 0, 1.0f, nullptr, p_after, 0);
}

// round 7
// speedup vs baseline: 3.3968x; 1.0334x over previous
#include <cuda_runtime.h>
#include <cuda_bf16.h>
#include <cstdint>

// Problem constants
#define BB 2
#define LL 2048
#define DD 2048
#define HH 16
#define HD 128
#define TT (BB*LL)            // 4096 tokens
#define QKVN (3*DD)           // 6144
#define OUT_ELEMS ((long)TT*DD)          // 8388608
#define SCORE_ELEMS ((long)BB*HH*LL*LL)  // 134217728

// Scratch (device globals; no allocation allowed)
__device__ float g_xn[TT*DD];
__device__ float g_qkv[TT*QKVN];
__device__ float g_attn[TT*DD];
__device__ float g_after[TT*DD];
__device__ float g_yn[TT*DD];
__device__ float g_hidden[TT*DD];
__device__ float g_hg[TT*DD];
// tf32-rounded weight copies
__device__ float g_wqkv_t[(long)QKVN*DD];
__device__ float g_wout_t[(long)DD*DD];
__device__ float g_win_t[(long)DD*DD];
__device__ float g_whid_t[(long)DD*DD];
__device__ float g_wgate_t[(long)DD*DD];

__device__ __forceinline__ uint32_t f2tf32(float f) {
    uint32_t u;
    asm("cvt.rna.tf32.f32 %0, %1;" : "=r"(u) : "f"(f));
    return u;
}
__device__ __forceinline__ float round_tf32(float f) {
    return __uint_as_float(f2tf32(f));
}

// ---------------------------------------------------------------------------
// Weight pre-conversion: fp32 -> tf32-rounded fp32 bits
// ---------------------------------------------------------------------------
__global__ void cvt_tf32_kernel(const float* __restrict__ src,
                                float* __restrict__ dst, int n4) {
    int i = blockIdx.x * blockDim.x + threadIdx.x;
    if (i < n4) {
        float4 v = ((const float4*)src)[i];
        v.x = round_tf32(v.x); v.y = round_tf32(v.y);
        v.z = round_tf32(v.z); v.w = round_tf32(v.w);
        ((float4*)dst)[i] = v;
    }
}

// ---------------------------------------------------------------------------
// Block reductions (256 threads = 8 warps)
// ---------------------------------------------------------------------------
__device__ __forceinline__ float block_reduce_max(float v, float* red) {
    int lane = threadIdx.x & 31, wid = threadIdx.x >> 5;
    #pragma unroll
    for (int o = 16; o; o >>= 1) v = fmaxf(v, __shfl_xor_sync(0xffffffffu, v, o));
    if (lane == 0) red[wid] = v;
    __syncthreads();
    if (wid == 0) {
        float u = (lane < 8) ? red[lane] : -3.4e38f;
        #pragma unroll
        for (int o = 4; o; o >>= 1) u = fmaxf(u, __shfl_xor_sync(0xffffffffu, u, o));
        if (lane == 0) red[0] = u;
    }
    __syncthreads();
    float r = red[0];
    __syncthreads();
    return r;
}

__device__ __forceinline__ float block_reduce_sum(float v, float* red) {
    int lane = threadIdx.x & 31, wid = threadIdx.x >> 5;
    #pragma unroll
    for (int o = 16; o; o >>= 1) v += __shfl_xor_sync(0xffffffffu, v, o);
    if (lane == 0) red[wid] = v;
    __syncthreads();
    if (wid == 0) {
        float u = (lane < 8) ? red[lane] : 0.f;
        #pragma unroll
        for (int o = 4; o; o >>= 1) u += __shfl_xor_sync(0xffffffffu, u, o);
        if (lane == 0) red[0] = u;
    }
    __syncthreads();
    float r = red[0];
    __syncthreads();
    return r;
}

// ---------------------------------------------------------------------------
// RMSNorm: one block per token row of D=2048; output rounded to tf32 bits
// (only ever consumed as a GEMM A-operand, so rounding here is numerically
//  identical to converting in the GEMM mainloop).
// ---------------------------------------------------------------------------
__global__ void rmsnorm_kernel(const float* __restrict__ x,
                               const float* __restrict__ g,
                               float* __restrict__ y) {
    __shared__ float red[32];
    long row = blockIdx.x;
    const float* xr = x + row * DD;
    float* yr = y + row * DD;
    int tid = threadIdx.x;

    float4 v0 = *(const float4*)&xr[tid * 4];
    float4 v1 = *(const float4*)&xr[1024 + tid * 4];
    float ss = v0.x*v0.x + v0.y*v0.y + v0.z*v0.z + v0.w*v0.w
             + v1.x*v1.x + v1.y*v1.y + v1.z*v1.z + v1.w*v1.w;
    ss = block_reduce_sum(ss, red);
    float norm = rsqrtf(ss * (1.0f / DD) + 1e-6f);

    float4 g0 = *(const float4*)&g[tid * 4];
    float4 g1 = *(const float4*)&g[1024 + tid * 4];
    float4 o0, o1;
    o0.x = round_tf32(v0.x * norm * g0.x); o0.y = round_tf32(v0.y * norm * g0.y);
    o0.z = round_tf32(v0.z * norm * g0.z); o0.w = round_tf32(v0.w * norm * g0.w);
    o1.x = round_tf32(v1.x * norm * g1.x); o1.y = round_tf32(v1.y * norm * g1.y);
    o1.z = round_tf32(v1.z * norm * g1.z); o1.w = round_tf32(v1.w * norm * g1.w);
    *(float4*)&yr[tid * 4] = o0;
    *(float4*)&yr[1024 + tid * 4] = o1;
}

// ---------------------------------------------------------------------------
// Row softmax over rows of length L=2048 (already at DRAM roofline).
// Output stays fp32 (it is a checked output of the problem).
// ---------------------------------------------------------------------------
__global__ void softmax_kernel(float* __restrict__ S) {
    __shared__ float red[32];
    long row = blockIdx.x;
    float* p = S + row * (long)LL;
    int tid = threadIdx.x;

    float4 v0 = *(const float4*)&p[tid * 4];
    float4 v1 = *(const float4*)&p[1024 + tid * 4];
    float m = fmaxf(fmaxf(fmaxf(v0.x, v0.y), fmaxf(v0.z, v0.w)),
                    fmaxf(fmaxf(v1.x, v1.y), fmaxf(v1.z, v1.w)));
    m = block_reduce_max(m, red);

    v0.x = __expf(v0.x - m); v0.y = __expf(v0.y - m);
    v0.z = __expf(v0.z - m); v0.w = __expf(v0.w - m);
    v1.x = __expf(v1.x - m); v1.y = __expf(v1.y - m);
    v1.z = __expf(v1.z - m); v1.w = __expf(v1.w - m);

    float s = v0.x + v0.y + v0.z + v0.w + v1.x + v1.y + v1.z + v1.w;
    s = block_reduce_sum(s, red);
    float inv = 1.0f / s;

    v0.x *= inv; v0.y *= inv; v0.z *= inv; v0.w *= inv;
    v1.x *= inv; v1.y *= inv; v1.z *= inv; v1.w *= inv;
    *(float4*)&p[tid * 4] = v0;
    *(float4*)&p[1024 + tid * 4] = v1;
}

// ---------------------------------------------------------------------------
// TF32 tensor-core GEMM with cp.async double buffering.
//   TB=true : C = epi( A[M,K] * W[N,K]^T )   (NT, both K-major)
//   TB=false: C = epi( A[M,K] * B[K,N] )     (NN)
// CVTA: convert A fragments in mainloop (only for fp32 A = scores);
//       otherwise operands are pre-rounded tf32 bits and load directly.
// ROUNDC: round epilogue output to tf32 bits (when C feeds another GEMM).
// Block tile 128x128x32, 256 threads = 8 warps (2x4), warp tile 64x32.
// ---------------------------------------------------------------------------
__device__ __forceinline__ void cp16(float* smem_dst, const float* gmem_src) {
    uint32_t d = (uint32_t)__cvta_generic_to_shared(smem_dst);
    asm volatile("cp.async.cg.shared.global [%0], [%1], 16;\n"
                 :: "r"(d), "l"(gmem_src));
}

__device__ __forceinline__ void mma_tf32(float* c, uint32_t a0, uint32_t a1,
                                         uint32_t a2, uint32_t a3,
                                         uint32_t b0, uint32_t b1) {
    asm volatile(
        "mma.sync.aligned.m16n8k8.row.col.f32.tf32.tf32.f32 "
        "{%0,%1,%2,%3}, {%4,%5,%6,%7}, {%8,%9}, {%0,%1,%2,%3};"
        : "+f"(c[0]), "+f"(c[1]), "+f"(c[2]), "+f"(c[3])
        : "r"(a0), "r"(a1), "r"(a2), "r"(a3), "r"(b0), "r"(b1));
}

template<bool TB, bool CVTA, bool ROUNDC>
__global__ __launch_bounds__(256, 2)
void gemm_tc(const float* __restrict__ A, const float* __restrict__ Bm,
             float* __restrict__ C,
             int K, int lda, int ldb, int ldc,
             int zH,
             long sAb, long sAh, long sBb, long sBh, long sCb, long sCh,
             float scale,
             const float* __restrict__ mulp,
             const float* __restrict__ addp,
             int relu) {
    constexpr int PA = 36;                     // floats per A row (m-major)
    constexpr int ASZ = 128 * PA;              // one A buffer
    constexpr int PBNN = 136;                  // floats per B row (k-major, NN)
    constexpr int BSZ = TB ? 128 * PA : 32 * PBNN;

    extern __shared__ float smem[];
    float* As = smem;                  // 2 buffers
    float* Bs = smem + 2 * ASZ;        // 2 buffers

    int z = blockIdx.z;
    int zb = z / zH, zh = z % zH;
    A  += zb * sAb + zh * sAh;
    Bm += zb * sBb + zh * sBh;
    C  += zb * sCb + zh * sCh;
    const float* mp = mulp ? (mulp + zb * sCb + zh * sCh) : nullptr;
    const float* ap = addp ? (addp + zb * sCb + zh * sCh) : nullptr;

    int tid = threadIdx.x;
    int lane = tid & 31, warp = tid >> 5;
    int wm = warp >> 2;         // 0..1
    int wn = warp & 3;          // 0..3
    int g = lane >> 2, tig = lane & 3;
    int m_base = wm * 64, n_base = wn * 32;
    int row0 = blockIdx.y * 128;
    int col0 = blockIdx.x * 128;

    float acc[4][4][4];
    #pragma unroll
    for (int mi = 0; mi < 4; mi++)
        #pragma unroll
        for (int ni = 0; ni < 4; ni++)
            #pragma unroll
            for (int r = 0; r < 4; r++) acc[mi][ni][r] = 0.f;

    int ar = tid >> 3;              // 0..31: m (A) / n (B-NT) base row
    int akq = (tid & 7) * 4;        // k offset within 32

    auto issue_tile = [&](int k0, int buf) {
        float* Ab = As + buf * ASZ;
        #pragma unroll
        for (int t = 0; t < 4; t++) {
            int r = ar + t * 32;
            cp16(&Ab[r * PA + akq], &A[(long)(row0 + r) * lda + k0 + akq]);
        }
        float* Bb = Bs + buf * BSZ;
        if (TB) {
            #pragma unroll
            for (int t = 0; t < 4; t++) {
                int r = ar + t * 32;
                cp16(&Bb[r * PA + akq], &Bm[(long)(col0 + r) * ldb + k0 + akq]);
            }
        } else {
            #pragma unroll
            for (int t = 0; t < 4; t++) {
                int q = tid + t * 256;
                int r = q >> 5;             // k row 0..31
                int c = (q & 31) * 4;       // col 0..124
                cp16(&Bb[r * PBNN + c], &Bm[(long)(k0 + r) * ldb + col0 + c]);
            }
        }
        asm volatile("cp.async.commit_group;\n" ::);
    };

    int nk = K >> 5;
    issue_tile(0, 0);

    for (int i = 0; i < nk; i++) {
        if (i + 1 < nk) {
            issue_tile((i + 1) << 5, (i + 1) & 1);
            asm volatile("cp.async.wait_group 1;\n" ::);
        } else {
            asm volatile("cp.async.wait_group 0;\n" ::);
        }
        __syncthreads();

        const float* Ab = As + (i & 1) * ASZ;
        const float* Bb = Bs + (i & 1) * BSZ;

        #pragma unroll
        for (int kk = 0; kk < 32; kk += 8) {
            uint32_t af[4][4], bf[4][2];
            #pragma unroll
            for (int mi = 0; mi < 4; mi++) {
                int mr = m_base + mi * 16 + g;
                if (CVTA) {
                    af[mi][0] = f2tf32(Ab[mr * PA + kk + tig]);
                    af[mi][1] = f2tf32(Ab[(mr + 8) * PA + kk + tig]);
                    af[mi][2] = f2tf32(Ab[mr * PA + kk + tig + 4]);
                    af[mi][3] = f2tf32(Ab[(mr + 8) * PA + kk + tig + 4]);
                } else {
                    af[mi][0] = __float_as_uint(Ab[mr * PA + kk + tig]);
                    af[mi][1] = __float_as_uint(Ab[(mr + 8) * PA + kk + tig]);
                    af[mi][2] = __float_as_uint(Ab[mr * PA + kk + tig + 4]);
                    af[mi][3] = __float_as_uint(Ab[(mr + 8) * PA + kk + tig + 4]);
                }
            }
            #pragma unroll
            for (int ni = 0; ni < 4; ni++) {
                int nc = n_base + ni * 8 + g;
                if (TB) {
                    bf[ni][0] = __float_as_uint(Bb[nc * PA + kk + tig]);
                    bf[ni][1] = __float_as_uint(Bb[nc * PA + kk + tig + 4]);
                } else {
                    bf[ni][0] = __float_as_uint(Bb[(kk + tig) * PBNN + nc]);
                    bf[ni][1] = __float_as_uint(Bb[(kk + tig + 4) * PBNN + nc]);
                }
            }
            #pragma unroll
            for (int mi = 0; mi < 4; mi++)
                #pragma unroll
                for (int ni = 0; ni < 4; ni++)
                    mma_tf32(acc[mi][ni], af[mi][0], af[mi][1], af[mi][2],
                             af[mi][3], bf[ni][0], bf[ni][1]);
        }
        __syncthreads();
    }

    // --- epilogue ---
    #pragma unroll
    for (int mi = 0; mi < 4; mi++) {
        #pragma unroll
        for (int half = 0; half < 2; half++) {
            int r = row0 + m_base + mi * 16 + g + half * 8;
            #pragma unroll
            for (int ni = 0; ni < 4; ni++) {
                int c = col0 + n_base + ni * 8 + tig * 2;
                long idx = (long)r * ldc + c;
                float2 v;
                v.x = acc[mi][ni][half * 2 + 0] * scale;
                v.y = acc[mi][ni][half * 2 + 1] * scale;
                if (mp) {
                    float2 m2 = *(const float2*)&mp[idx];
                    v.x *= m2.x; v.y *= m2.y;
                }
                if (relu) { v.x = fmaxf(v.x, 0.f); v.y = fmaxf(v.y, 0.f); }
                if (ap) {
                    float2 a2 = *(const float2*)&ap[idx];
                    v.x += a2.x; v.y += a2.y;
                }
                if (ROUNDC) { v.x = round_tf32(v.x); v.y = round_tf32(v.y); }
                *(float2*)&C[idx] = v;
            }
        }
    }
}

// ---------------------------------------------------------------------------
extern "C" void kernel_launch(void* const* d_in, const int* in_sizes, int n_in,
                              void* d_out, int out_size) {
    (void)in_sizes; (void)n_in; (void)out_size;
    const float* x       = (const float*)d_in[0];
    const float* w_qkv   = (const float*)d_in[1];
    const float* w_out   = (const float*)d_in[2];
    const float* w_in    = (const float*)d_in[3];
    const float* w_hid   = (const float*)d_in[4];
    const float* w_gate  = (const float*)d_in[5];
    const float* g_attng = (const float*)d_in[6];
    const float* g_ffng  = (const float*)d_in[7];
    float* out = (float*)d_out;
    float* scores = out + OUT_ELEMS;

    float *p_xn, *p_qkv, *p_attn, *p_after, *p_yn, *p_hidden, *p_hg;
    float *p_wqkv, *p_wout, *p_win, *p_whid, *p_wgate;
    cudaGetSymbolAddress((void**)&p_xn, g_xn);
    cudaGetSymbolAddress((void**)&p_qkv, g_qkv);
    cudaGetSymbolAddress((void**)&p_attn, g_attn);
    cudaGetSymbolAddress((void**)&p_after, g_after);
    cudaGetSymbolAddress((void**)&p_yn, g_yn);
    cudaGetSymbolAddress((void**)&p_hidden, g_hidden);
    cudaGetSymbolAddress((void**)&p_hg, g_hg);
    cudaGetSymbolAddress((void**)&p_wqkv, g_wqkv_t);
    cudaGetSymbolAddress((void**)&p_wout, g_wout_t);
    cudaGetSymbolAddress((void**)&p_win, g_win_t);
    cudaGetSymbolAddress((void**)&p_whid, g_whid_t);
    cudaGetSymbolAddress((void**)&p_wgate, g_wgate_t);

    const int SMEM_NT = (2 * 128 * 36 + 2 * 128 * 36) * 4;   // 73728
    const int SMEM_NN = (2 * 128 * 36 + 2 * 32 * 136) * 4;   // 71680
    cudaFuncSetAttribute(gemm_tc<true, false, true>,
        cudaFuncAttributeMaxDynamicSharedMemorySize, SMEM_NT);
    cudaFuncSetAttribute(gemm_tc<true, false, false>,
        cudaFuncAttributeMaxDynamicSharedMemorySize, SMEM_NT);
    cudaFuncSetAttribute(gemm_tc<false, true, true>,
        cudaFuncAttributeMaxDynamicSharedMemorySize, SMEM_NN);

    const long sQb = (long)LL * QKVN;  // batch stride inside qkv
    const long sSb = (long)HH * LL * LL;
    const long sSh = (long)LL * LL;
    const float iscale = 0.08838834764831845f;  // 1/sqrt(128)

    // 0) weight pre-conversion to tf32 bit patterns
    {
        int n4q = (QKVN * DD) / 4, n4 = (DD * DD) / 4;
        cvt_tf32_kernel<<<(n4q + 255) / 256, 256>>>(w_qkv, p_wqkv, n4q);
        cvt_tf32_kernel<<<(n4 + 255) / 256, 256>>>(w_out, p_wout, n4);
        cvt_tf32_kernel<<<(n4 + 255) / 256, 256>>>(w_in, p_win, n4);
        cvt_tf32_kernel<<<(n4 + 255) / 256, 256>>>(w_hid, p_whid, n4);
        cvt_tf32_kernel<<<(n4 + 255) / 256, 256>>>(w_gate, p_wgate, n4);
    }

    // 1) attn-branch RMSNorm (output tf32-rounded)
    rmsnorm_kernel<<<TT, 256>>>(x, g_attng, p_xn);

    // 2) QKV GEMM: [4096,2048] x [6144,2048]^T  (output rounded: feeds S/PV)
    gemm_tc<true, false, true><<<dim3(QKVN / 128, TT / 128, 1), 256, SMEM_NT>>>(
        p_xn, p_wqkv, p_qkv, DD, DD, DD, QKVN,
        1, 0, 0, 0, 0, 0, 0, 1.0f, nullptr, nullptr, 0);

    // 3) S = Q K^T / sqrt(HD), per (b,h): M=N=2048, K=128 (fp32 out: scores)
    gemm_tc<true, false, false><<<dim3(LL / 128, LL / 128, BB * HH), 256, SMEM_NT>>>(
        p_qkv, p_qkv + DD, scores, HD, QKVN, QKVN, LL,
        HH, sQb, HD, sQb, HD, sSb, sSh, iscale, nullptr, nullptr, 0);

    // 4) row softmax on scores (in place; checked output stays fp32)
    softmax_kernel<<<BB * HH * LL, 256>>>(scores);

    // 5) attn = P V, per (b,h): M=2048, N=128, K=2048 (NN; cvt A in loop)
    gemm_tc<false, true, true><<<dim3(1, LL / 128, BB * HH), 256, SMEM_NN>>>(
        scores, p_qkv + 2 * DD, p_attn, LL, LL, QKVN, DD,
        HH, sSb, sSh, sQb, HD, (long)LL * DD, HD, 1.0f, nullptr, nullptr, 0);

    // 6) after_attn = x + attn * w_out^T  (fp32 out: residual)
    gemm_tc<true, false, false><<<dim3(DD / 128, TT / 128, 1), 256, SMEM_NT>>>(
        p_attn, p_wout, p_after, DD, DD, DD, DD,
        1, 0, 0, 0, 0, 0, 0, 1.0f, nullptr, x, 0);

    // 7) FFN-branch RMSNorm (output tf32-rounded)
    rmsnorm_kernel<<<TT, 256>>>(p_after, g_ffng, p_yn);

    // 8) hidden = relu(yn * w_in^T)  (rounded: feeds GEMMs 9)
    gemm_tc<true, false, true><<<dim3(DD / 128, TT / 128, 1), 256, SMEM_NT>>>(
        p_yn, p_win, p_hidden, DD, DD, DD, DD,
        1, 0, 0, 0, 0, 0, 0, 1.0f, nullptr, nullptr, 1);

    // 9) hg = hidden * (hidden * w_gate^T)  (rounded: feeds GEMM 10)
    gemm_tc<true, false, true><<<dim3(DD / 128, TT / 128, 1), 256, SMEM_NT>>>(
        p_hidden, p_wgate, p_hg, DD, DD, DD, DD,
        1, 0, 0, 0, 0, 0, 0, 1.0f, p_hidden, nullptr, 0);

    // 10) out = after_attn + hg * w_hidden^T  (fp32 final output)
    gemm_tc<true, false, false><<<dim3(DD / 128, TT / 128, 1), 256, SMEM_NT>>>(
        p_hg, p_whid, out, DD, DD, DD, DD,
        1, 0, 0, 0, 0, 0, 0, 1.0f, nullptr, p_after, 0);
}